// round 14
// baseline (speedup 1.0000x reference)
#include <cuda_runtime.h>
#include <math.h>

#define N_IMG   64
#define C_PRED  85
#define HDIM    32
#define HW      1024
#define NCLS    80
#define CONF_TH 0.25f
#define NMS_TH  0.35f
#define MAXK    64          // per-class candidate cap (mean ~6 for this data)

// Output layout (float32): [ bboxes: N*HW*6 ][ keep: N*HW ]
#define BBOX_ELEMS ((size_t)N_IMG * HW * 6)

// Scratch (allocation-free __device__ globals; zero-initialized at load,
// counters reset in-kernel for graph replays)
__device__ int                g_nv  [N_IMG];
__device__ unsigned long long g_lkey[N_IMG * HW];   // [cls:7][score:32][idxinv:10]
__device__ float4             g_lbox[N_IMG * HW];

// ================= Kernel 1: decode + compact candidate list =================
__global__ __launch_bounds__(128)
void decode_kernel(const float* __restrict__ preds, float* __restrict__ out)
{
    const int n = blockIdx.y;                          // image
    const int t = blockIdx.x * 128 + threadIdx.x;      // cell 0..1023
    const int lane = threadIdx.x & 31;

    const float* p = preds + (size_t)n * C_PRED * HW + t;

    const float pobj = p[0];
    const float r0 = p[1 * HW];
    const float r1 = p[2 * HW];
    const float r2 = p[3 * HW];
    const float r3 = p[4 * HW];

    float mx = p[5 * HW];
    int   am = 0;
    #pragma unroll 8
    for (int c = 1; c < NCLS; ++c) {
        float v = p[(5 + c) * HW];
        if (v > mx) { mx = v; am = c; }   // strict '>' => first max index (jnp.argmax)
    }
    const float score = pobj * mx;

    const int gw = t & (HDIM - 1);
    const int gh = t >> 5;

    const float bw  = 1.0f / (1.0f + expf(-r2));
    const float bh  = 1.0f / (1.0f + expf(-r3));
    const float bcx = (tanhf(r0) + (float)gw) * (1.0f / 32.0f);  // /32 exact
    const float bcy = (tanhf(r1) + (float)gh) * (1.0f / 32.0f);

    const float x1 = bcx - 0.5f * bw;
    const float y1 = bcy - 0.5f * bh;
    const float x2 = bcx + 0.5f * bw;
    const float y2 = bcy + 0.5f * bh;

    float* ob = out + ((size_t)n * HW + t) * 6;
    ob[0] = x1; ob[1] = y1; ob[2] = x2; ob[3] = y2;
    ob[4] = score; ob[5] = (float)am;

    // warp-aggregated push into the per-image compact list
    const bool valid = score > CONF_TH;
    const unsigned msk = __ballot_sync(0xffffffffu, valid);
    if (msk) {
        const int leader = __ffs(msk) - 1;
        int base = 0;
        if (lane == leader) base = atomicAdd(&g_nv[n], __popc(msk));
        base = __shfl_sync(0xffffffffu, base, leader);
        if (valid) {
            const int slot = base + __popc(msk & ((1u << lane) - 1u));
            g_lkey[n * HW + slot] =
                ((unsigned long long)am << 42)
                | ((unsigned long long)__float_as_uint(score) << 10)
                | (unsigned long long)(HW - 1 - t);
            g_lbox[n * HW + slot] = make_float4(x1, y1, x2, y2);
        }
    }
}

// ================= Kernel 2: one CTA per image, all-smem NMS =================
__global__ __launch_bounds__(512)
void nms_kernel(float* __restrict__ out)
{
    __shared__ unsigned long long skey[HW];            // compact keys     8 KB
    __shared__ float4             sbox[HW];            // compact boxes   16 KB
    __shared__ unsigned short     bucket[NCLS * MAXK]; // class buckets   10 KB
    __shared__ int                bcnt[NCLS];
    __shared__ unsigned char      skeep[HW];
    __shared__ int                snv;

    const int n    = blockIdx.x;
    const int tid  = threadIdx.x;
    const int wp   = tid >> 5;
    const int lane = tid & 31;

    if (tid < NCLS) bcnt[tid] = 0;
    skeep[tid]       = 0;
    skeep[tid + 512] = 0;
    if (tid == 0) { snv = g_nv[n]; g_nv[n] = 0; }      // read + reset for replay
    __syncthreads();
    const int nv = snv;

    // parallel contiguous load + smem class bucketing
    for (int i = tid; i < nv; i += 512) {
        const unsigned long long key = g_lkey[n * HW + i];
        skey[i] = key;
        sbox[i] = g_lbox[n * HW + i];
        const int cls = (int)(key >> 42);
        const int slot = atomicAdd(&bcnt[cls], 1);
        if (slot < MAXK) bucket[cls * MAXK + slot] = (unsigned short)i;
    }
    __syncthreads();

    // 16 warps x 5 classes: lane-parallel matrix greedy, all smem/registers
    for (int c = wp; c < NCLS; c += 16) {
        int k = bcnt[c];
        if (k > MAXK) k = MAXK;
        if (k == 0) continue;

        if (k <= 32) {
            int    ci = 0;
            unsigned long long key = 0;
            float4 box = make_float4(0.f, 0.f, 0.f, 0.f);
            if (lane < k) {
                ci  = bucket[c * MAXK + lane];
                key = skey[ci];
                box = sbox[ci];
            }
            const float area = (box.z - box.x) * (box.w - box.y);

            // rank = #{keys strictly greater} (stable argsort(-score); keys distinct)
            int rnk = 0;
            #pragma unroll 4
            for (int j = 0; j < k; ++j) {
                const unsigned long long kj = __shfl_sync(0xffffffffu, key, j);
                if (kj > key) ++rnk;                   // garbage for lane>=k; masked below
            }

            // suppression row over LANE indices (self bit set: IoU(self,self)=1)
            unsigned M = 0;
            for (int j = 0; j < k; ++j) {
                const int bj = bucket[c * MAXK + j];   // broadcast LDS
                const float4 kb = sbox[bj];            // broadcast LDS128
                float iw = fminf(box.z, kb.z) - fmaxf(box.x, kb.x);
                iw = fmaxf(iw, 0.0f);
                float ih = fminf(box.w, kb.w) - fmaxf(box.y, kb.y);
                ih = fmaxf(ih, 0.0f);
                const float inter = iw * ih;
                const float kba = (kb.z - kb.x) * (kb.w - kb.y);
                const float iou = inter / (area + kba - inter + 1e-9f);
                if (iou > NMS_TH) M |= (1u << j);
            }

            // greedy in rank order: registers + shuffles only
            unsigned alive = (k == 32) ? 0xffffffffu : ((1u << k) - 1u);
            bool keptme = false;
            for (int r = 0; r < k; ++r) {
                if (!alive) break;
                const unsigned bsrc =
                    __ballot_sync(0xffffffffu, (lane < k) && (rnk == r));
                const int src = __ffs(bsrc) - 1;       // exactly one bit
                if (alive & (1u << src)) {
                    const unsigned Ms = __shfl_sync(0xffffffffu, M, src);
                    if (lane == src) keptme = true;
                    alive &= ~Ms;
                    alive &= ~(1u << src);
                }
            }
            if (lane < k && keptme) {
                const int cell = (HW - 1) - (int)(key & (HW - 1));
                skeep[cell] = 1;
            }
        } else if (lane == 0) {
            // rare fallback: serial selection-based greedy (32 < k <= 64)
            unsigned long long alive = (k >= 64) ? ~0ull : ((1ull << k) - 1ull);
            while (alive) {
                unsigned long long best = 0; int bs = 0;
                unsigned long long m = alive;
                while (m) {
                    const int j = __ffsll((long long)m) - 1;
                    m &= m - 1;
                    const unsigned long long kj = skey[bucket[c * MAXK + j]];
                    if (kj > best) { best = kj; bs = j; }
                }
                const int cell = (HW - 1) - (int)(best & (HW - 1));
                skeep[cell] = 1;
                alive &= ~(1ull << bs);

                const float4 cbb = sbox[bucket[c * MAXK + bs]];
                const float  ca = (cbb.z - cbb.x) * (cbb.w - cbb.y);
                m = alive;
                while (m) {
                    const int j = __ffsll((long long)m) - 1;
                    m &= m - 1;
                    const float4 kb = sbox[bucket[c * MAXK + j]];
                    float iw = fminf(cbb.z, kb.z) - fmaxf(cbb.x, kb.x);
                    iw = fmaxf(iw, 0.0f);
                    float ih = fminf(cbb.w, kb.w) - fmaxf(cbb.y, kb.y);
                    ih = fmaxf(ih, 0.0f);
                    const float inter = iw * ih;
                    const float kba = (kb.z - kb.x) * (kb.w - kb.y);
                    const float iou = inter / (ca + kba - inter + 1e-9f);
                    if (iou > NMS_TH) alive &= ~(1ull << j);
                }
            }
        }
    }
    __syncthreads();

    // coalesced keep writeout (entire slice)
    float* keep = out + BBOX_ELEMS + (size_t)n * HW;
    keep[tid]       = (float)skeep[tid];
    keep[tid + 512] = (float)skeep[tid + 512];
}

extern "C" void kernel_launch(void* const* d_in, const int* in_sizes, int n_in,
                              void* d_out, int out_size)
{
    (void)in_sizes; (void)n_in; (void)out_size;
    const float* preds = (const float*)d_in[0];
    float* out = (float*)d_out;
    decode_kernel<<<dim3(HW / 128, N_IMG), 128>>>(preds, out);
    nms_kernel<<<N_IMG, 512>>>(out);
}

// round 15
// speedup vs baseline: 1.3574x; 1.3574x over previous
#include <cuda_runtime.h>
#include <math.h>

#define N_IMG   64
#define C_PRED  85
#define HDIM    32
#define HW      1024
#define NCLS    80
#define CONF_TH 0.25f
#define NMS_TH  0.35f
#define MAXK    64          // per-class candidate cap (mean ~6 for this data)
#define NMS_SUB 4           // NMS CTAs per image; CTA sub handles classes c with (c&3)==sub
#define LCLS    (NCLS / NMS_SUB)   // 20 local classes per NMS CTA

// Output layout (float32): [ bboxes: N*HW*6 ][ keep: N*HW ]
#define BBOX_ELEMS ((size_t)N_IMG * HW * 6)

// Scratch (allocation-free __device__ globals; zero-initialized at load,
// counters reset in-kernel for graph replays)
__device__ int                g_nv  [N_IMG];
__device__ int                g_done[N_IMG];
__device__ unsigned long long g_lkey[N_IMG * HW];   // [cls:7][score:32][idxinv:10]
__device__ float4             g_lbox[N_IMG * HW];

// ================= Kernel 1: decode + compact candidate list =================
__global__ __launch_bounds__(128)
void decode_kernel(const float* __restrict__ preds, float* __restrict__ out)
{
    const int n = blockIdx.y;                          // image
    const int t = blockIdx.x * 128 + threadIdx.x;      // cell 0..1023
    const int lane = threadIdx.x & 31;

    const float* p = preds + (size_t)n * C_PRED * HW + t;

    const float pobj = p[0];
    const float r0 = p[1 * HW];
    const float r1 = p[2 * HW];
    const float r2 = p[3 * HW];
    const float r3 = p[4 * HW];

    float mx = p[5 * HW];
    int   am = 0;
    #pragma unroll 8
    for (int c = 1; c < NCLS; ++c) {
        float v = p[(5 + c) * HW];
        if (v > mx) { mx = v; am = c; }   // strict '>' => first max index (jnp.argmax)
    }
    const float score = pobj * mx;

    const int gw = t & (HDIM - 1);
    const int gh = t >> 5;

    const float bw  = 1.0f / (1.0f + expf(-r2));
    const float bh  = 1.0f / (1.0f + expf(-r3));
    const float bcx = (tanhf(r0) + (float)gw) * (1.0f / 32.0f);  // /32 exact
    const float bcy = (tanhf(r1) + (float)gh) * (1.0f / 32.0f);

    const float x1 = bcx - 0.5f * bw;
    const float y1 = bcy - 0.5f * bh;
    const float x2 = bcx + 0.5f * bw;
    const float y2 = bcy + 0.5f * bh;

    float* ob = out + ((size_t)n * HW + t) * 6;
    ob[0] = x1; ob[1] = y1; ob[2] = x2; ob[3] = y2;
    ob[4] = score; ob[5] = (float)am;

    // zero-fill keep mask (NMS kernel scatter-writes the 1s)
    out[BBOX_ELEMS + (size_t)n * HW + t] = 0.0f;

    // warp-aggregated push into the per-image compact list
    const bool valid = score > CONF_TH;
    const unsigned msk = __ballot_sync(0xffffffffu, valid);
    if (msk) {
        const int leader = __ffs(msk) - 1;
        int base = 0;
        if (lane == leader) base = atomicAdd(&g_nv[n], __popc(msk));
        base = __shfl_sync(0xffffffffu, base, leader);
        if (valid) {
            const int slot = base + __popc(msk & ((1u << lane) - 1u));
            g_lkey[n * HW + slot] =
                ((unsigned long long)am << 42)
                | ((unsigned long long)__float_as_uint(score) << 10)
                | (unsigned long long)(HW - 1 - t);
            g_lbox[n * HW + slot] = make_float4(x1, y1, x2, y2);
        }
    }
}

// ================= Kernel 2: 4 CTAs per image, 20 classes each =================
__global__ __launch_bounds__(256)
void nms_kernel(float* __restrict__ out)
{
    __shared__ unsigned long long skey[HW];            // staged keys (our classes)
    __shared__ float4             sbox[HW];            // staged boxes (our classes)
    __shared__ unsigned short     bucket[LCLS * MAXK];
    __shared__ int                bcnt[LCLS];
    __shared__ int                snv;
    __shared__ unsigned char      sRL[8 * 32];         // per-warp rank -> slot
    __shared__ unsigned           Msm[8 * 32];         // per-warp suppression rows

    const int sub = blockIdx.x;                        // 0..3
    const int n   = blockIdx.y;
    const int tid = threadIdx.x;
    const int wp   = tid >> 5;
    const int lane = tid & 31;

    if (tid < LCLS) bcnt[tid] = 0;
    if (tid == 0) snv = g_nv[n];
    __syncthreads();
    const int nv = snv;

    // coalesced scan of the compact list; stage + bucket only our classes
    for (int i = tid; i < nv; i += 256) {
        const unsigned long long key = g_lkey[n * HW + i];
        const int cls = (int)(key >> 42);
        if ((cls & (NMS_SUB - 1)) == sub) {
            skey[i] = key;
            sbox[i] = g_lbox[n * HW + i];
            const int lc = cls >> 2;
            const int slot = atomicAdd(&bcnt[lc], 1);
            if (slot < MAXK) bucket[lc * MAXK + slot] = (unsigned short)i;
        }
    }
    __syncthreads();

    float* keep = out + BBOX_ELEMS + (size_t)n * HW;

    // 8 warps x 2.5 classes: LDS-based matrix greedy (no ballot/shfl in hot path)
    for (int lc = wp; lc < LCLS; lc += 8) {
        int k = bcnt[lc];
        if (k > MAXK) k = MAXK;
        if (k == 0) continue;

        if (k <= 32) {
            // lane == slot
            unsigned long long key = 0;
            float4 box = make_float4(0.f, 0.f, 0.f, 0.f);
            if (lane < k) {
                const int ii = bucket[lc * MAXK + lane];
                key = skey[ii];
                box = sbox[ii];
            }
            const float area = (box.z - box.x) * (box.w - box.y);

            // rank = #{keys strictly greater} (stable argsort(-score); keys distinct)
            int rnk = 0;
            for (int j = 0; j < k; ++j) {
                const unsigned long long kj = skey[bucket[lc * MAXK + j]]; // bcast LDS
                if (lane < k && kj > key) ++rnk;
            }
            if (lane < k) sRL[wp * 32 + rnk] = (unsigned char)lane;

            // suppression row over SLOT indices (self bit set: IoU(self,self)=1)
            unsigned M = 0;
            if (lane < k) {
                for (int j = 0; j < k; ++j) {
                    const float4 kb = sbox[bucket[lc * MAXK + j]];        // bcast LDS128
                    float iw = fminf(box.z, kb.z) - fmaxf(box.x, kb.x);
                    iw = fmaxf(iw, 0.0f);
                    float ih = fminf(box.w, kb.w) - fmaxf(box.y, kb.y);
                    ih = fmaxf(ih, 0.0f);
                    const float inter = iw * ih;
                    const float kba = (kb.z - kb.x) * (kb.w - kb.y);
                    const float iou = inter / (area + kba - inter + 1e-9f);
                    if (iou > NMS_TH) M |= (1u << j);
                }
                Msm[wp * 32 + lane] = M;
            }
            __syncwarp();

            // uniform scalar greedy in rank order: LDS-only, no warp-sync ops
            unsigned alive = (k == 32) ? 0xffffffffu : ((1u << k) - 1u);
            unsigned kept = 0;
            for (int r = 0; r < k && alive; ++r) {
                const int s = sRL[wp * 32 + r];                           // bcast LDS
                if ((alive >> s) & 1u) {
                    kept  |= (1u << s);
                    alive &= ~Msm[wp * 32 + s];   // self bit clears s too
                }
            }
            if (lane < k && ((kept >> lane) & 1u))
                keep[(HW - 1) - (int)(key & (HW - 1))] = 1.0f;
            __syncwarp();   // staging reused next class
        } else if (lane == 0) {
            // rare fallback: serial selection-based greedy (32 < k <= 64)
            unsigned long long alive = (k >= 64) ? ~0ull : ((1ull << k) - 1ull);
            while (alive) {
                unsigned long long best = 0; int bs = 0;
                unsigned long long m = alive;
                while (m) {
                    const int j = __ffsll((long long)m) - 1;
                    m &= m - 1;
                    const unsigned long long kj = skey[bucket[lc * MAXK + j]];
                    if (kj > best) { best = kj; bs = j; }
                }
                keep[(HW - 1) - (int)(best & (HW - 1))] = 1.0f;
                alive &= ~(1ull << bs);

                const float4 cbb = sbox[bucket[lc * MAXK + bs]];
                const float  ca = (cbb.z - cbb.x) * (cbb.w - cbb.y);
                m = alive;
                while (m) {
                    const int j = __ffsll((long long)m) - 1;
                    m &= m - 1;
                    const float4 kb = sbox[bucket[lc * MAXK + j]];
                    float iw = fminf(cbb.z, kb.z) - fmaxf(cbb.x, kb.x);
                    iw = fmaxf(iw, 0.0f);
                    float ih = fminf(cbb.w, kb.w) - fmaxf(cbb.y, kb.y);
                    ih = fmaxf(ih, 0.0f);
                    const float inter = iw * ih;
                    const float kba = (kb.z - kb.x) * (kb.w - kb.y);
                    const float iou = inter / (ca + kba - inter + 1e-9f);
                    if (iou > NMS_TH) alive &= ~(1ull << j);
                }
            }
        }
    }

    // replay-state reset: last NMS CTA of this image clears the counter
    __syncthreads();
    if (tid == 0) {
        __threadfence();
        if (atomicAdd(&g_done[n], 1) == NMS_SUB - 1) {
            g_nv[n]   = 0;
            g_done[n] = 0;
        }
    }
}

extern "C" void kernel_launch(void* const* d_in, const int* in_sizes, int n_in,
                              void* d_out, int out_size)
{
    (void)in_sizes; (void)n_in; (void)out_size;
    const float* preds = (const float*)d_in[0];
    float* out = (float*)d_out;
    decode_kernel<<<dim3(HW / 128, N_IMG), 128>>>(preds, out);
    nms_kernel<<<dim3(NMS_SUB, N_IMG), 256>>>(out);
}